// round 3
// baseline (speedup 1.0000x reference)
#include <cuda_runtime.h>

// ---------------- problem constants ----------------
#define HWT    80
#define NVOX   (HWT*HWT*HWT)      // 512000
#define CIN    32
#define DIM    48                  // heads*hd
#define NHEADS 8
#define HD     6
#define NMOT   (NHEADS*3*NVOX)     // 12288000
#define LN_EPS 1e-5f

// attn smem: per-head k tile [6 d][18 lines][82 t]
#define DSTRIDE 1476               // 18*82
#define KS_WORDS (HD*DSTRIDE)      // 8856
#define SMEM_ATTN (KS_WORDS*4)     // 35424 B

// ---------------- packed fp32x2 helpers (sm_103a) ----------------
#define FMA_F32X2(d, a, b, c) \
    asm("fma.rn.f32x2 %0, %1, %2, %3;" : "=l"(d) : "l"(a), "l"(b), "l"(c))
#define PACK_F32X2(out, lo, hi) \
    asm("mov.b64 %0, {%1, %2};" : "=l"(out) : "f"(lo), "f"(hi))
#define UNPACK_F32X2(lo, hi, in) \
    asm("mov.b64 {%0, %1}, %2;" : "=f"(lo), "=f"(hi) : "l"(in))

// ---------------- scratch (static device globals) ----------------
// d-major layout: [48][NVOX]
__device__ float g_q[(size_t)DIM*NVOX];
__device__ float g_k[(size_t)DIM*NVOX];
__device__ float g_partial[1600*NHEADS];   // 12800 per-block score partials

// ============ kernel A: Linear(32->48) + LayerNorm, 2 voxels/thread =========
__global__ __launch_bounds__(128) void proj_kernel(
    const float* __restrict__ F, const float* __restrict__ M,
    const float* __restrict__ Wm, const float* __restrict__ bias,
    const float* __restrict__ lnw, const float* __restrict__ lnb)
{
    __shared__ float sWt[CIN*DIM];   // transposed: [c][d], d contiguous
    __shared__ float sB[DIM], sLW[DIM], sLB[DIM];

    const int tid = threadIdx.x;
    for (int i = tid; i < DIM*CIN; i += 128) {
        const int d = i / CIN, c = i - d*CIN;
        sWt[c*DIM + d] = Wm[i];
    }
    if (tid < DIM) { sB[tid] = bias[tid]; sLW[tid] = lnw[tid]; sLB[tid] = lnb[tid]; }
    __syncthreads();

    const float* __restrict__ src = blockIdx.y ? M : F;
    float* __restrict__ dst = blockIdx.y ? g_k : g_q;

    const int v0 = blockIdx.x * 256 + tid;
    const int v1 = v0 + 128;

    // packed accumulators over d-pairs, two voxels
    unsigned long long acc0[DIM/2], acc1[DIM/2];
#pragma unroll
    for (int j = 0; j < DIM/2; j++) {
        unsigned long long b2;
        PACK_F32X2(b2, sB[2*j], sB[2*j+1]);
        acc0[j] = b2; acc1[j] = b2;
    }

#pragma unroll 4
    for (int c = 0; c < CIN; c++) {
        const float x0 = src[(size_t)c*NVOX + v0];
        const float x1 = src[(size_t)c*NVOX + v1];
        unsigned long long xx0, xx1;
        PACK_F32X2(xx0, x0, x0);
        PACK_F32X2(xx1, x1, x1);
        const ulonglong2* __restrict__ wr = (const ulonglong2*)(sWt + c*DIM);
#pragma unroll
        for (int j2 = 0; j2 < DIM/4; j2++) {
            const ulonglong2 w2 = wr[j2];
            FMA_F32X2(acc0[2*j2  ], w2.x, xx0, acc0[2*j2  ]);
            FMA_F32X2(acc0[2*j2+1], w2.y, xx0, acc0[2*j2+1]);
            FMA_F32X2(acc1[2*j2  ], w2.x, xx1, acc1[2*j2  ]);
            FMA_F32X2(acc1[2*j2+1], w2.y, xx1, acc1[2*j2+1]);
        }
    }

    // layernorm + d-major coalesced writeout, per voxel
#pragma unroll
    for (int vv = 0; vv < 2; vv++) {
        const unsigned long long* acc = vv ? acc1 : acc0;
        const int v = vv ? v1 : v0;
        float sum = 0.f, sq = 0.f;
#pragma unroll
        for (int j = 0; j < DIM/2; j++) {
            float a, b;
            UNPACK_F32X2(a, b, acc[j]);
            sum += a + b;
            sq = fmaf(a, a, sq);
            sq = fmaf(b, b, sq);
        }
        const float mu = sum * (1.f/48.f);
        const float rs = rsqrtf(sq * (1.f/48.f) - mu*mu + LN_EPS);
#pragma unroll
        for (int j = 0; j < DIM/2; j++) {
            float a, b;
            UNPACK_F32X2(a, b, acc[j]);
            dst[(size_t)(2*j  )*NVOX + v] = (a - mu) * rs * sLW[2*j  ] + sLB[2*j  ];
            dst[(size_t)(2*j+1)*NVOX + v] = (b - mu) * rs * sLW[2*j+1] + sLB[2*j+1];
        }
    }
}

// ======== kernel B: per-(head, 4w-strip) 27-neighbor attention ==============
__global__ __launch_bounds__(320, 3) void attn_kernel(
    const float* __restrict__ rpb, float* __restrict__ out)
{
    extern __shared__ float ks[];          // [6 d][18 lines][82 t]
    __shared__ float s_rpb[27];
    __shared__ float red[10];

    const int tid  = threadIdx.x;
    const int bx   = blockIdx.x;           // 0..1599
    const int head = blockIdx.y;            // 0..7
    const int h    = bx / 20;
    const int w0   = (bx - h*20) * 4;
    const int hd6  = head * HD;

    if (tid < 27) s_rpb[tid] = rpb[head*27 + tid];

    // zero t-halo slots
    for (int i = tid; i < HD*18*2; i += 320) {
        const int d = i / 36, r = i - d*36;
        const int line = r >> 1, e = r & 1;
        ks[d*DSTRIDE + line*82 + (e ? 81 : 0)] = 0.f;
    }
    // coalesced d-major fill: 6 d x 18 lines x 80 t
    for (int i = tid; i < HD*18*HWT; i += 320) {
        const int d = i / (18*HWT);
        const int r = i - d*(18*HWT);
        const int line = r / HWT;
        const int t = r - line*HWT;
        const int lh = h + line/6 - 1;
        const int lw = w0 + line%6 - 1;
        float val = 0.f;
        if (lh >= 0 && lh < HWT && lw >= 0 && lw < HWT)
            val = g_k[(size_t)(hd6 + d)*NVOX + (lh*HWT + lw)*HWT + t];
        ks[d*DSTRIDE + line*82 + t + 1] = val;
    }
    __syncthreads();

    const int t  = tid % HWT;
    const int wl = tid / HWT;               // 0..3
    const int w  = w0 + wl;
    const int v  = (h*HWT + w)*HWT + t;

    float qv[HD];
#pragma unroll
    for (int d = 0; d < HD; d++)
        qv[d] = g_q[(size_t)(hd6 + d)*NVOX + v];

    float attn[27];
#pragma unroll
    for (int o = 0; o < 27; o++) {
        const int oi = o / 9, oj = (o / 3) % 3, ol = o % 3;
        const int line = oi*6 + wl + oj;
        const float* __restrict__ kp = ks + line*82 + t + ol;
        float a = 0.f;
#pragma unroll
        for (int d = 0; d < HD; d++)
            a = fmaf(qv[d], kp[d*DSTRIDE], a);
        attn[o] = a + s_rpb[o];
    }

    float sc = attn[14];   // pre-softmax score channel (K^3/2 + 1)

    // softmax over 27
    float m = attn[0];
#pragma unroll
    for (int o = 1; o < 27; o++) m = fmaxf(m, attn[o]);
    float ssum = 0.f;
#pragma unroll
    for (int o = 0; o < 27; o++) { attn[o] = __expf(attn[o] - m); ssum += attn[o]; }
    const float inv = __fdividef(1.f, ssum);

    // expectation over displacements
    float mx = 0.f, my = 0.f, mz = 0.f;
#pragma unroll
    for (int o = 0; o < 27; o++) {
        const int oi = o / 9, oj = (o / 3) % 3, ol = o % 3;
        if (oi == 2) mx += attn[o]; else if (oi == 0) mx -= attn[o];
        if (oj == 2) my += attn[o]; else if (oj == 0) my -= attn[o];
        if (ol == 2) mz += attn[o]; else if (ol == 0) mz -= attn[o];
    }

    out[(size_t)(head*3 + 0)*NVOX + v] = mx * inv;
    out[(size_t)(head*3 + 1)*NVOX + v] = my * inv;
    out[(size_t)(head*3 + 2)*NVOX + v] = mz * inv;

    // deterministic block reduction of score channel
#pragma unroll
    for (int off = 16; off; off >>= 1) sc += __shfl_down_sync(0xffffffffu, sc, off);
    if ((tid & 31) == 0) red[tid >> 5] = sc;
    __syncthreads();
    if (tid < 32) {
        float v2 = (tid < 10) ? red[tid] : 0.f;
#pragma unroll
        for (int off = 16; off; off >>= 1) v2 += __shfl_down_sync(0xffffffffu, v2, off);
        if (tid == 0) g_partial[head*1600 + bx] = v2;
    }
}

// ---------------- kernel C: deterministic final score reduction -------------
__global__ __launch_bounds__(256) void score_kernel(float* __restrict__ out)
{
    __shared__ double sd[256];
    const int tid = threadIdx.x;
    double a = 0.0;
    for (int i = tid; i < 1600*NHEADS; i += 256) a += (double)g_partial[i];
    sd[tid] = a;
    __syncthreads();
    for (int s = 128; s > 0; s >>= 1) {
        if (tid < s) sd[tid] += sd[tid + s];
        __syncthreads();
    }
    if (tid == 0) out[NMOT] = (float)(sd[0] * (1.0 / 4096000.0));
}

// ---------------- launch -----------------------------------------------------
extern "C" void kernel_launch(void* const* d_in, const int* in_sizes, int n_in,
                              void* d_out, int out_size)
{
    const float* F   = (const float*)d_in[0];
    const float* M   = (const float*)d_in[1];
    const float* Wm  = (const float*)d_in[2];
    const float* b   = (const float*)d_in[3];
    const float* lnw = (const float*)d_in[4];
    const float* lnb = (const float*)d_in[5];
    const float* rpb = (const float*)d_in[6];
    float* out = (float*)d_out;

    cudaFuncSetAttribute(attn_kernel, cudaFuncAttributeMaxDynamicSharedMemorySize, SMEM_ATTN);

    proj_kernel<<<dim3(NVOX/256, 2, 1), 128>>>(F, M, Wm, b, lnw, lnb);
    attn_kernel<<<dim3(1600, NHEADS, 1), 320, SMEM_ATTN>>>(rpb, out);
    if (out_size > NMOT) score_kernel<<<1, 256>>>(out);
}

// round 4
// speedup vs baseline: 1.0004x; 1.0004x over previous
#include <cuda_runtime.h>

// ---------------- problem constants ----------------
#define HWT    80
#define NVOX   (HWT*HWT*HWT)      // 512000
#define CIN    32
#define DIM    48                  // heads*hd
#define NHEADS 8
#define HD     6
#define NMOT   (NHEADS*3*NVOX)     // 12288000
#define LN_EPS 1e-5f

// attn smem: per-head k tile [6 d][18 lines][82 t]
#define DSTRIDE 1476               // 18*82
#define KS_WORDS (HD*DSTRIDE)      // 8856
#define SMEM_ATTN (KS_WORDS*4)     // 35424 B

// ---------------- packed fp32x2 helpers (sm_103a) ----------------
#define FMA_F32X2(d, a, b, c) \
    asm("fma.rn.f32x2 %0, %1, %2, %3;" : "=l"(d) : "l"(a), "l"(b), "l"(c))
#define PACK_F32X2(out, lo, hi) \
    asm("mov.b64 %0, {%1, %2};" : "=l"(out) : "f"(lo), "f"(hi))
#define UNPACK_F32X2(lo, hi, in) \
    asm("mov.b64 {%0, %1}, %2;" : "=f"(lo), "=f"(hi) : "l"(in))

// ---------------- scratch (static device globals) ----------------
// d-major layout: [48][NVOX]
__device__ float g_q[(size_t)DIM*NVOX];
__device__ float g_k[(size_t)DIM*NVOX];
__device__ float g_partial[1600*NHEADS];   // 12800 per-block score partials

// ============ kernel A: Linear(32->48) + LayerNorm, 2 voxels/thread =========
__global__ __launch_bounds__(128) void proj_kernel(
    const float* __restrict__ F, const float* __restrict__ M,
    const float* __restrict__ Wm, const float* __restrict__ bias,
    const float* __restrict__ lnw, const float* __restrict__ lnb)
{
    __shared__ float sWt[CIN*DIM];   // transposed: [c][d], d contiguous
    __shared__ float sB[DIM], sLW[DIM], sLB[DIM];

    const int tid = threadIdx.x;
    for (int i = tid; i < DIM*CIN; i += 128) {
        const int d = i / CIN, c = i - d*CIN;
        sWt[c*DIM + d] = Wm[i];
    }
    if (tid < DIM) { sB[tid] = bias[tid]; sLW[tid] = lnw[tid]; sLB[tid] = lnb[tid]; }
    __syncthreads();

    const float* __restrict__ src = blockIdx.y ? M : F;
    float* __restrict__ dst = blockIdx.y ? g_k : g_q;

    const int v0 = blockIdx.x * 256 + tid;
    const int v1 = v0 + 128;

    // packed accumulators over d-pairs, two voxels
    unsigned long long acc0[DIM/2], acc1[DIM/2];
#pragma unroll
    for (int j = 0; j < DIM/2; j++) {
        unsigned long long b2;
        PACK_F32X2(b2, sB[2*j], sB[2*j+1]);
        acc0[j] = b2; acc1[j] = b2;
    }

#pragma unroll 4
    for (int c = 0; c < CIN; c++) {
        const float x0 = src[(size_t)c*NVOX + v0];
        const float x1 = src[(size_t)c*NVOX + v1];
        unsigned long long xx0, xx1;
        PACK_F32X2(xx0, x0, x0);
        PACK_F32X2(xx1, x1, x1);
        const ulonglong2* __restrict__ wr = (const ulonglong2*)(sWt + c*DIM);
#pragma unroll
        for (int j2 = 0; j2 < DIM/4; j2++) {
            const ulonglong2 w2 = wr[j2];
            FMA_F32X2(acc0[2*j2  ], w2.x, xx0, acc0[2*j2  ]);
            FMA_F32X2(acc0[2*j2+1], w2.y, xx0, acc0[2*j2+1]);
            FMA_F32X2(acc1[2*j2  ], w2.x, xx1, acc1[2*j2  ]);
            FMA_F32X2(acc1[2*j2+1], w2.y, xx1, acc1[2*j2+1]);
        }
    }

    // layernorm + d-major coalesced writeout, per voxel
#pragma unroll
    for (int vv = 0; vv < 2; vv++) {
        const unsigned long long* acc = vv ? acc1 : acc0;
        const int v = vv ? v1 : v0;
        float sum = 0.f, sq = 0.f;
#pragma unroll
        for (int j = 0; j < DIM/2; j++) {
            float a, b;
            UNPACK_F32X2(a, b, acc[j]);
            sum += a + b;
            sq = fmaf(a, a, sq);
            sq = fmaf(b, b, sq);
        }
        const float mu = sum * (1.f/48.f);
        const float rs = rsqrtf(sq * (1.f/48.f) - mu*mu + LN_EPS);
#pragma unroll
        for (int j = 0; j < DIM/2; j++) {
            float a, b;
            UNPACK_F32X2(a, b, acc[j]);
            dst[(size_t)(2*j  )*NVOX + v] = (a - mu) * rs * sLW[2*j  ] + sLB[2*j  ];
            dst[(size_t)(2*j+1)*NVOX + v] = (b - mu) * rs * sLW[2*j+1] + sLB[2*j+1];
        }
    }
}

// ======== kernel B: per-(head, 4w-strip) 27-neighbor attention ==============
__global__ __launch_bounds__(320, 3) void attn_kernel(
    const float* __restrict__ rpb, float* __restrict__ out)
{
    extern __shared__ float ks[];          // [6 d][18 lines][82 t]
    __shared__ float s_rpb[27];
    __shared__ float red[10];

    const int tid  = threadIdx.x;
    const int bx   = blockIdx.x;           // 0..1599
    const int head = blockIdx.y;            // 0..7
    const int h    = bx / 20;
    const int w0   = (bx - h*20) * 4;
    const int hd6  = head * HD;

    if (tid < 27) s_rpb[tid] = rpb[head*27 + tid];

    // zero t-halo slots
    for (int i = tid; i < HD*18*2; i += 320) {
        const int d = i / 36, r = i - d*36;
        const int line = r >> 1, e = r & 1;
        ks[d*DSTRIDE + line*82 + (e ? 81 : 0)] = 0.f;
    }
    // coalesced d-major fill: 6 d x 18 lines x 80 t
    for (int i = tid; i < HD*18*HWT; i += 320) {
        const int d = i / (18*HWT);
        const int r = i - d*(18*HWT);
        const int line = r / HWT;
        const int t = r - line*HWT;
        const int lh = h + line/6 - 1;
        const int lw = w0 + line%6 - 1;
        float val = 0.f;
        if (lh >= 0 && lh < HWT && lw >= 0 && lw < HWT)
            val = g_k[(size_t)(hd6 + d)*NVOX + (lh*HWT + lw)*HWT + t];
        ks[d*DSTRIDE + line*82 + t + 1] = val;
    }
    __syncthreads();

    const int t  = tid % HWT;
    const int wl = tid / HWT;               // 0..3
    const int w  = w0 + wl;
    const int v  = (h*HWT + w)*HWT + t;

    float qv[HD];
#pragma unroll
    for (int d = 0; d < HD; d++)
        qv[d] = g_q[(size_t)(hd6 + d)*NVOX + v];

    float attn[27];
#pragma unroll
    for (int o = 0; o < 27; o++) {
        const int oi = o / 9, oj = (o / 3) % 3, ol = o % 3;
        const int line = oi*6 + wl + oj;
        const float* __restrict__ kp = ks + line*82 + t + ol;
        float a = 0.f;
#pragma unroll
        for (int d = 0; d < HD; d++)
            a = fmaf(qv[d], kp[d*DSTRIDE], a);
        attn[o] = a + s_rpb[o];
    }

    float sc = attn[14];   // pre-softmax score channel (K^3/2 + 1)

    // softmax over 27
    float m = attn[0];
#pragma unroll
    for (int o = 1; o < 27; o++) m = fmaxf(m, attn[o]);
    float ssum = 0.f;
#pragma unroll
    for (int o = 0; o < 27; o++) { attn[o] = __expf(attn[o] - m); ssum += attn[o]; }
    const float inv = __fdividef(1.f, ssum);

    // expectation over displacements
    float mx = 0.f, my = 0.f, mz = 0.f;
#pragma unroll
    for (int o = 0; o < 27; o++) {
        const int oi = o / 9, oj = (o / 3) % 3, ol = o % 3;
        if (oi == 2) mx += attn[o]; else if (oi == 0) mx -= attn[o];
        if (oj == 2) my += attn[o]; else if (oj == 0) my -= attn[o];
        if (ol == 2) mz += attn[o]; else if (ol == 0) mz -= attn[o];
    }

    out[(size_t)(head*3 + 0)*NVOX + v] = mx * inv;
    out[(size_t)(head*3 + 1)*NVOX + v] = my * inv;
    out[(size_t)(head*3 + 2)*NVOX + v] = mz * inv;

    // deterministic block reduction of score channel
#pragma unroll
    for (int off = 16; off; off >>= 1) sc += __shfl_down_sync(0xffffffffu, sc, off);
    if ((tid & 31) == 0) red[tid >> 5] = sc;
    __syncthreads();
    if (tid < 32) {
        float v2 = (tid < 10) ? red[tid] : 0.f;
#pragma unroll
        for (int off = 16; off; off >>= 1) v2 += __shfl_down_sync(0xffffffffu, v2, off);
        if (tid == 0) g_partial[head*1600 + bx] = v2;
    }
}

// ---------------- kernel C: deterministic final score reduction -------------
__global__ __launch_bounds__(256) void score_kernel(float* __restrict__ out)
{
    __shared__ double sd[256];
    const int tid = threadIdx.x;
    double a = 0.0;
    for (int i = tid; i < 1600*NHEADS; i += 256) a += (double)g_partial[i];
    sd[tid] = a;
    __syncthreads();
    for (int s = 128; s > 0; s >>= 1) {
        if (tid < s) sd[tid] += sd[tid + s];
        __syncthreads();
    }
    if (tid == 0) out[NMOT] = (float)(sd[0] * (1.0 / 4096000.0));
}

// ---------------- launch -----------------------------------------------------
extern "C" void kernel_launch(void* const* d_in, const int* in_sizes, int n_in,
                              void* d_out, int out_size)
{
    const float* F   = (const float*)d_in[0];
    const float* M   = (const float*)d_in[1];
    const float* Wm  = (const float*)d_in[2];
    const float* b   = (const float*)d_in[3];
    const float* lnw = (const float*)d_in[4];
    const float* lnb = (const float*)d_in[5];
    const float* rpb = (const float*)d_in[6];
    float* out = (float*)d_out;

    cudaFuncSetAttribute(attn_kernel, cudaFuncAttributeMaxDynamicSharedMemorySize, SMEM_ATTN);

    proj_kernel<<<dim3(NVOX/256, 2, 1), 128>>>(F, M, Wm, b, lnw, lnb);
    attn_kernel<<<dim3(1600, NHEADS, 1), 320, SMEM_ATTN>>>(rpb, out);
    if (out_size > NMOT) score_kernel<<<1, 256>>>(out);
}

// round 5
// speedup vs baseline: 1.0007x; 1.0003x over previous
#include <cuda_runtime.h>

// ---------------- problem constants ----------------
#define HWT    80
#define NVOX   (HWT*HWT*HWT)      // 512000
#define CIN    32
#define DIM    48                  // heads*hd
#define NHEADS 8
#define HD     6
#define NMOT   (NHEADS*3*NVOX)     // 12288000
#define LN_EPS 1e-5f

// attn smem: per-head k tile [6 d][18 lines][82 t]
#define DSTRIDE 1476               // 18*82
#define KS_WORDS (HD*DSTRIDE)      // 8856
#define SMEM_ATTN (KS_WORDS*4)     // 35424 B

// ---------------- packed fp32x2 helpers (sm_103a) ----------------
#define FMA_F32X2(d, a, b, c) \
    asm("fma.rn.f32x2 %0, %1, %2, %3;" : "=l"(d) : "l"(a), "l"(b), "l"(c))
#define PACK_F32X2(out, lo, hi) \
    asm("mov.b64 %0, {%1, %2};" : "=l"(out) : "f"(lo), "f"(hi))
#define UNPACK_F32X2(lo, hi, in) \
    asm("mov.b64 {%0, %1}, %2;" : "=f"(lo), "=f"(hi) : "l"(in))

// ---------------- scratch (static device globals) ----------------
// d-major layout: [48][NVOX]
__device__ float g_q[(size_t)DIM*NVOX];
__device__ float g_k[(size_t)DIM*NVOX];
__device__ float g_partial[1600*NHEADS];   // 12800 per-block score partials

// ============ kernel A: Linear(32->48) + LayerNorm, 2 voxels/thread =========
__global__ __launch_bounds__(128) void proj_kernel(
    const float* __restrict__ F, const float* __restrict__ M,
    const float* __restrict__ Wm, const float* __restrict__ bias,
    const float* __restrict__ lnw, const float* __restrict__ lnb)
{
    __shared__ float sWt[CIN*DIM];   // transposed: [c][d], d contiguous
    __shared__ float sB[DIM], sLW[DIM], sLB[DIM];

    const int tid = threadIdx.x;
    for (int i = tid; i < DIM*CIN; i += 128) {
        const int d = i / CIN, c = i - d*CIN;
        sWt[c*DIM + d] = Wm[i];
    }
    if (tid < DIM) { sB[tid] = bias[tid]; sLW[tid] = lnw[tid]; sLB[tid] = lnb[tid]; }
    __syncthreads();

    const float* __restrict__ src = blockIdx.y ? M : F;
    float* __restrict__ dst = blockIdx.y ? g_k : g_q;

    const int v0 = blockIdx.x * 256 + tid;
    const int v1 = v0 + 128;

    // packed accumulators over d-pairs, two voxels
    unsigned long long acc0[DIM/2], acc1[DIM/2];
#pragma unroll
    for (int j = 0; j < DIM/2; j++) {
        unsigned long long b2;
        PACK_F32X2(b2, sB[2*j], sB[2*j+1]);
        acc0[j] = b2; acc1[j] = b2;
    }

#pragma unroll 4
    for (int c = 0; c < CIN; c++) {
        const float x0 = src[(size_t)c*NVOX + v0];
        const float x1 = src[(size_t)c*NVOX + v1];
        unsigned long long xx0, xx1;
        PACK_F32X2(xx0, x0, x0);
        PACK_F32X2(xx1, x1, x1);
        const ulonglong2* __restrict__ wr = (const ulonglong2*)(sWt + c*DIM);
#pragma unroll
        for (int j2 = 0; j2 < DIM/4; j2++) {
            const ulonglong2 w2 = wr[j2];
            FMA_F32X2(acc0[2*j2  ], w2.x, xx0, acc0[2*j2  ]);
            FMA_F32X2(acc0[2*j2+1], w2.y, xx0, acc0[2*j2+1]);
            FMA_F32X2(acc1[2*j2  ], w2.x, xx1, acc1[2*j2  ]);
            FMA_F32X2(acc1[2*j2+1], w2.y, xx1, acc1[2*j2+1]);
        }
    }

    // layernorm + d-major coalesced writeout, per voxel
#pragma unroll
    for (int vv = 0; vv < 2; vv++) {
        const unsigned long long* acc = vv ? acc1 : acc0;
        const int v = vv ? v1 : v0;
        float sum = 0.f, sq = 0.f;
#pragma unroll
        for (int j = 0; j < DIM/2; j++) {
            float a, b;
            UNPACK_F32X2(a, b, acc[j]);
            sum += a + b;
            sq = fmaf(a, a, sq);
            sq = fmaf(b, b, sq);
        }
        const float mu = sum * (1.f/48.f);
        const float rs = rsqrtf(sq * (1.f/48.f) - mu*mu + LN_EPS);
#pragma unroll
        for (int j = 0; j < DIM/2; j++) {
            float a, b;
            UNPACK_F32X2(a, b, acc[j]);
            dst[(size_t)(2*j  )*NVOX + v] = (a - mu) * rs * sLW[2*j  ] + sLB[2*j  ];
            dst[(size_t)(2*j+1)*NVOX + v] = (b - mu) * rs * sLW[2*j+1] + sLB[2*j+1];
        }
    }
}

// ======== kernel B: per-(head, 4w-strip) 27-neighbor attention ==============
__global__ __launch_bounds__(320, 3) void attn_kernel(
    const float* __restrict__ rpb, float* __restrict__ out)
{
    extern __shared__ float ks[];          // [6 d][18 lines][82 t]
    __shared__ float s_rpb[27];
    __shared__ float red[10];

    const int tid  = threadIdx.x;
    const int bx   = blockIdx.x;           // 0..1599
    const int head = blockIdx.y;            // 0..7
    const int h    = bx / 20;
    const int w0   = (bx - h*20) * 4;
    const int hd6  = head * HD;

    if (tid < 27) s_rpb[tid] = rpb[head*27 + tid];

    // zero t-halo slots
    for (int i = tid; i < HD*18*2; i += 320) {
        const int d = i / 36, r = i - d*36;
        const int line = r >> 1, e = r & 1;
        ks[d*DSTRIDE + line*82 + (e ? 81 : 0)] = 0.f;
    }
    // coalesced d-major fill: 6 d x 18 lines x 80 t
    for (int i = tid; i < HD*18*HWT; i += 320) {
        const int d = i / (18*HWT);
        const int r = i - d*(18*HWT);
        const int line = r / HWT;
        const int t = r - line*HWT;
        const int lh = h + line/6 - 1;
        const int lw = w0 + line%6 - 1;
        float val = 0.f;
        if (lh >= 0 && lh < HWT && lw >= 0 && lw < HWT)
            val = g_k[(size_t)(hd6 + d)*NVOX + (lh*HWT + lw)*HWT + t];
        ks[d*DSTRIDE + line*82 + t + 1] = val;
    }
    __syncthreads();

    const int t  = tid % HWT;
    const int wl = tid / HWT;               // 0..3
    const int w  = w0 + wl;
    const int v  = (h*HWT + w)*HWT + t;

    float qv[HD];
#pragma unroll
    for (int d = 0; d < HD; d++)
        qv[d] = g_q[(size_t)(hd6 + d)*NVOX + v];

    float attn[27];
#pragma unroll
    for (int o = 0; o < 27; o++) {
        const int oi = o / 9, oj = (o / 3) % 3, ol = o % 3;
        const int line = oi*6 + wl + oj;
        const float* __restrict__ kp = ks + line*82 + t + ol;
        float a = 0.f;
#pragma unroll
        for (int d = 0; d < HD; d++)
            a = fmaf(qv[d], kp[d*DSTRIDE], a);
        attn[o] = a + s_rpb[o];
    }

    float sc = attn[14];   // pre-softmax score channel (K^3/2 + 1)

    // softmax over 27
    float m = attn[0];
#pragma unroll
    for (int o = 1; o < 27; o++) m = fmaxf(m, attn[o]);
    float ssum = 0.f;
#pragma unroll
    for (int o = 0; o < 27; o++) { attn[o] = __expf(attn[o] - m); ssum += attn[o]; }
    const float inv = __fdividef(1.f, ssum);

    // expectation over displacements
    float mx = 0.f, my = 0.f, mz = 0.f;
#pragma unroll
    for (int o = 0; o < 27; o++) {
        const int oi = o / 9, oj = (o / 3) % 3, ol = o % 3;
        if (oi == 2) mx += attn[o]; else if (oi == 0) mx -= attn[o];
        if (oj == 2) my += attn[o]; else if (oj == 0) my -= attn[o];
        if (ol == 2) mz += attn[o]; else if (ol == 0) mz -= attn[o];
    }

    out[(size_t)(head*3 + 0)*NVOX + v] = mx * inv;
    out[(size_t)(head*3 + 1)*NVOX + v] = my * inv;
    out[(size_t)(head*3 + 2)*NVOX + v] = mz * inv;

    // deterministic block reduction of score channel
#pragma unroll
    for (int off = 16; off; off >>= 1) sc += __shfl_down_sync(0xffffffffu, sc, off);
    if ((tid & 31) == 0) red[tid >> 5] = sc;
    __syncthreads();
    if (tid < 32) {
        float v2 = (tid < 10) ? red[tid] : 0.f;
#pragma unroll
        for (int off = 16; off; off >>= 1) v2 += __shfl_down_sync(0xffffffffu, v2, off);
        if (tid == 0) g_partial[head*1600 + bx] = v2;
    }
}

// ---------------- kernel C: deterministic final score reduction -------------
__global__ __launch_bounds__(256) void score_kernel(float* __restrict__ out)
{
    __shared__ double sd[256];
    const int tid = threadIdx.x;
    double a = 0.0;
    for (int i = tid; i < 1600*NHEADS; i += 256) a += (double)g_partial[i];
    sd[tid] = a;
    __syncthreads();
    for (int s = 128; s > 0; s >>= 1) {
        if (tid < s) sd[tid] += sd[tid + s];
        __syncthreads();
    }
    if (tid == 0) out[NMOT] = (float)(sd[0] * (1.0 / 4096000.0));
}

// ---------------- launch -----------------------------------------------------
extern "C" void kernel_launch(void* const* d_in, const int* in_sizes, int n_in,
                              void* d_out, int out_size)
{
    const float* F   = (const float*)d_in[0];
    const float* M   = (const float*)d_in[1];
    const float* Wm  = (const float*)d_in[2];
    const float* b   = (const float*)d_in[3];
    const float* lnw = (const float*)d_in[4];
    const float* lnb = (const float*)d_in[5];
    const float* rpb = (const float*)d_in[6];
    float* out = (float*)d_out;

    cudaFuncSetAttribute(attn_kernel, cudaFuncAttributeMaxDynamicSharedMemorySize, SMEM_ATTN);

    proj_kernel<<<dim3(NVOX/256, 2, 1), 128>>>(F, M, Wm, b, lnw, lnb);
    attn_kernel<<<dim3(1600, NHEADS, 1), 320, SMEM_ATTN>>>(rpb, out);
    if (out_size > NMOT) score_kernel<<<1, 256>>>(out);
}

// round 6
// speedup vs baseline: 1.4384x; 1.4375x over previous
#include <cuda_runtime.h>

// ---------------- problem constants ----------------
#define HWT    80
#define NVOX   (HWT*HWT*HWT)      // 512000
#define CIN    32
#define DIM    48
#define NHEADS 8
#define HD     6
#define NMOT   (NHEADS*3*NVOX)
#define LN_EPS 1e-5f

typedef unsigned long long ull;

// ---------------- packed fp32x2 helpers (sm_103a) ----------------
#define FMA_F32X2(d, a, b, c) \
    asm("fma.rn.f32x2 %0, %1, %2, %3;" : "=l"(d) : "l"(a), "l"(b), "l"(c))
#define PACK_F32X2(out, lo, hi) \
    asm("mov.b64 %0, {%1, %2};" : "=l"(out) : "f"(lo), "f"(hi))
#define UNPACK_F32X2(lo, hi, in) \
    asm("mov.b64 {%0, %1}, %2;" : "=f"(lo), "=f"(hi) : "l"(in))

// ---------------- scratch (static device globals) ----------------
// q/k pair-interleaved: [24 d-pairs][NVOX][2]
__device__ float g_q[(size_t)DIM*NVOX];
__device__ float g_k[(size_t)DIM*NVOX];
__device__ float g_partial[1600*NHEADS];

// ============ kernel A: Linear(32->48)+LN, 4 vox x 12 d per thread ==========
__global__ __launch_bounds__(256, 3) void proj_kernel(
    const float* __restrict__ F, const float* __restrict__ M,
    const float* __restrict__ Wm, const float* __restrict__ bias,
    const float* __restrict__ lnw, const float* __restrict__ lnb)
{
    __shared__ float sWt[CIN*DIM];     // [c][d]
    __shared__ float sX[CIN*256];      // [c][256 voxels]
    __shared__ float sB[DIM], sLW[DIM], sLB[DIM];

    const int tid = threadIdx.x;
    for (int i = tid; i < DIM*CIN; i += 256) {
        const int d = i / CIN, c = i - d*CIN;
        sWt[c*DIM + d] = Wm[i];
    }
    if (tid < DIM) { sB[tid] = bias[tid]; sLW[tid] = lnw[tid]; sLB[tid] = lnb[tid]; }

    const float* __restrict__ src = blockIdx.y ? M : F;
    float* __restrict__ dst = blockIdx.y ? g_k : g_q;
    const int v0 = blockIdx.x * 256;

    // stage x tile [32 c][256 v]
    {
        const float4* __restrict__ s4 = (const float4*)src;
        float4* __restrict__ x4 = (float4*)sX;
        for (int i = tid; i < CIN*64; i += 256) {
            const int c = i >> 6, j = i & 63;
            x4[c*64 + j] = s4[(size_t)c*(NVOX/4) + (v0 >> 2) + j];
        }
    }
    __syncthreads();

    const int g = tid & 3;     // d-group: d in [12g, 12g+12)
    const int q = tid >> 2;    // voxel quad: v in [v0+4q, v0+4q+4)

    ull acc[24];               // [vox 4][d-pair 6]
#pragma unroll
    for (int j = 0; j < 6; j++) {
        ull b2;
        PACK_F32X2(b2, sB[12*g + 2*j], sB[12*g + 2*j + 1]);
        acc[j] = b2; acc[6+j] = b2; acc[12+j] = b2; acc[18+j] = b2;
    }

#pragma unroll 2
    for (int c = 0; c < CIN; c++) {
        const float4 xq = *(const float4*)(sX + c*256 + 4*q);
        ull xx0, xx1, xx2, xx3;
        PACK_F32X2(xx0, xq.x, xq.x);
        PACK_F32X2(xx1, xq.y, xq.y);
        PACK_F32X2(xx2, xq.z, xq.z);
        PACK_F32X2(xx3, xq.w, xq.w);
        const ulonglong2* __restrict__ wr = (const ulonglong2*)(sWt + c*DIM + 12*g);
#pragma unroll
        for (int j2 = 0; j2 < 3; j2++) {
            const ulonglong2 w2 = wr[j2];
            FMA_F32X2(acc[    2*j2  ], w2.x, xx0, acc[    2*j2  ]);
            FMA_F32X2(acc[    2*j2+1], w2.y, xx0, acc[    2*j2+1]);
            FMA_F32X2(acc[ 6 +2*j2  ], w2.x, xx1, acc[ 6 +2*j2  ]);
            FMA_F32X2(acc[ 6 +2*j2+1], w2.y, xx1, acc[ 6 +2*j2+1]);
            FMA_F32X2(acc[12 +2*j2  ], w2.x, xx2, acc[12 +2*j2  ]);
            FMA_F32X2(acc[12 +2*j2+1], w2.y, xx2, acc[12 +2*j2+1]);
            FMA_F32X2(acc[18 +2*j2  ], w2.x, xx3, acc[18 +2*j2  ]);
            FMA_F32X2(acc[18 +2*j2+1], w2.y, xx3, acc[18 +2*j2+1]);
        }
    }

    // layernorm stats: partial over this thread's 12 d, combine across the
    // 4 d-group lanes (same warp: lanes 4q'+g) via shfl_xor
    float mu[4], rs[4];
#pragma unroll
    for (int i = 0; i < 4; i++) {
        float sum = 0.f, sq = 0.f;
#pragma unroll
        for (int j = 0; j < 6; j++) {
            float a, b;
            UNPACK_F32X2(a, b, acc[i*6 + j]);
            sum += a + b;
            sq = fmaf(a, a, sq);
            sq = fmaf(b, b, sq);
        }
        sum += __shfl_xor_sync(0xffffffffu, sum, 1);
        sq  += __shfl_xor_sync(0xffffffffu, sq, 1);
        sum += __shfl_xor_sync(0xffffffffu, sum, 2);
        sq  += __shfl_xor_sync(0xffffffffu, sq, 2);
        mu[i] = sum * (1.f/48.f);
        rs[i] = rsqrtf(sq * (1.f/48.f) - mu[i]*mu[i] + LN_EPS);
    }

    // pair-interleaved writeout: dst[(p*NVOX + v)*2 + {0,1}], STG.128 x2 per pair
    const int vbase = v0 + 4*q;
#pragma unroll
    for (int j = 0; j < 6; j++) {
        const int d0 = 12*g + 2*j;
        const int p  = 6*g + j;
        const float w0l = sLW[d0], w1l = sLW[d0+1];
        const float b0l = sLB[d0], b1l = sLB[d0+1];
        float o[8];
#pragma unroll
        for (int i = 0; i < 4; i++) {
            float a, b;
            UNPACK_F32X2(a, b, acc[i*6 + j]);
            o[2*i  ] = (a - mu[i]) * rs[i] * w0l + b0l;
            o[2*i+1] = (b - mu[i]) * rs[i] * w1l + b1l;
        }
        float4* __restrict__ d4 = (float4*)(dst + ((size_t)p*NVOX + vbase)*2);
        d4[0] = make_float4(o[0], o[1], o[2], o[3]);
        d4[1] = make_float4(o[4], o[5], o[6], o[7]);
    }
}

// ======== kernel B: 27-neighbor attention, max-free streaming softmax =======
#define LSTR  82            // float2 units per line (80 + 2 halo)
#define D2STR (18*LSTR)     // 1476 float2 units per d-pair

__global__ __launch_bounds__(320, 4) void attn_kernel(
    const float* __restrict__ rpb, float* __restrict__ out)
{
    __shared__ float2 ks[3*D2STR];     // 35424 B: [3 d-pairs][18 lines][82 t]
    __shared__ float s_rpb[27];
    __shared__ float red[10];

    const int tid  = threadIdx.x;
    const int bx   = blockIdx.x;        // 0..1599
    const int head = blockIdx.y;        // 0..7
    const int h    = bx / 20;
    const int w0   = (bx - h*20) * 4;
    const int pb   = head * 3;          // d-pair base for this head

    if (tid < 27) s_rpb[tid] = rpb[head*27 + tid];

    // zero t-halo (t'=0 and t'=81): 3*18*2 = 108 units
    if (tid < 108) {
        const int d2 = tid / 36, r = tid - d2*36;
        const int line = r >> 1, e = r & 1;
        ks[d2*D2STR + line*LSTR + (e ? 81 : 0)] = make_float2(0.f, 0.f);
    }

    // coalesced pair fill: 3 d-pairs x 18 lines x 80 t  (LDG.64 each)
    const float2* __restrict__ gk2 = (const float2*)g_k;
    for (int i = tid; i < 3*18*80; i += 320) {
        const int d2 = i / 1440;
        const int r  = i - d2*1440;
        const int line = r / 80;
        const int t  = r - line*80;
        const int lh = h + line/6 - 1;
        const int lw = w0 + (line - (line/6)*6) - 1;
        float2 val = make_float2(0.f, 0.f);
        if (lh >= 0 && lh < HWT && lw >= 0 && lw < HWT)
            val = gk2[(size_t)(pb + d2)*NVOX + (lh*HWT + lw)*HWT + t];
        ks[d2*D2STR + line*LSTR + t + 1] = val;
    }

    // q load (before sync, overlaps fill)
    const int t  = tid % HWT;
    const int wl = tid / HWT;           // 0..3
    const int v  = (h*HWT + (w0 + wl))*HWT + t;
    const ull* __restrict__ gq2 = (const ull*)g_q;
    const ull q01 = gq2[(size_t)(pb + 0)*NVOX + v];
    const ull q23 = gq2[(size_t)(pb + 1)*NVOX + v];
    const ull q45 = gq2[(size_t)(pb + 2)*NVOX + v];
    __syncthreads();

    const ull* __restrict__ kb = (const ull*)ks;
    const ull z2 = 0ull;                // packed (+0,+0)
    float s = 0.f, mx = 0.f, my = 0.f, mz = 0.f, sc = 0.f;

#pragma unroll
    for (int o = 0; o < 27; o++) {
        const int oi = o / 9, oj = (o / 3) % 3, ol = o % 3;
        const int idx = (oi*6 + wl + oj)*LSTR + t + ol;
        ull a2;
        FMA_F32X2(a2, q01, kb[idx          ], z2);
        FMA_F32X2(a2, q23, kb[idx +   D2STR], a2);
        FMA_F32X2(a2, q45, kb[idx + 2*D2STR], a2);
        float alo, ahi;
        UNPACK_F32X2(alo, ahi, a2);
        const float a = alo + ahi + s_rpb[o];
        if (o == 14) sc = a;            // pre-softmax score channel
        const float e = __expf(a);      // max-free: |a| is O(10), safe in fp32
        s += e;
        if (oi == 0) mx -= e; else if (oi == 2) mx += e;
        if (oj == 0) my -= e; else if (oj == 2) my += e;
        if (ol == 0) mz -= e; else if (ol == 2) mz += e;
    }

    const float inv = __fdividef(1.f, s);
    out[(size_t)(head*3 + 0)*NVOX + v] = mx * inv;
    out[(size_t)(head*3 + 1)*NVOX + v] = my * inv;
    out[(size_t)(head*3 + 2)*NVOX + v] = mz * inv;

    // deterministic block reduction of score channel
#pragma unroll
    for (int off = 16; off; off >>= 1) sc += __shfl_down_sync(0xffffffffu, sc, off);
    if ((tid & 31) == 0) red[tid >> 5] = sc;
    __syncthreads();
    if (tid < 32) {
        float v2 = (tid < 10) ? red[tid] : 0.f;
#pragma unroll
        for (int off = 16; off; off >>= 1) v2 += __shfl_down_sync(0xffffffffu, v2, off);
        if (tid == 0) g_partial[head*1600 + bx] = v2;
    }
}

// ---------------- kernel C: deterministic final score reduction -------------
__global__ __launch_bounds__(256) void score_kernel(float* __restrict__ out)
{
    __shared__ double sd[256];
    const int tid = threadIdx.x;
    double a = 0.0;
    for (int i = tid; i < 1600*NHEADS; i += 256) a += (double)g_partial[i];
    sd[tid] = a;
    __syncthreads();
    for (int s = 128; s > 0; s >>= 1) {
        if (tid < s) sd[tid] += sd[tid + s];
        __syncthreads();
    }
    if (tid == 0) out[NMOT] = (float)(sd[0] * (1.0 / 4096000.0));
}

// ---------------- launch -----------------------------------------------------
extern "C" void kernel_launch(void* const* d_in, const int* in_sizes, int n_in,
                              void* d_out, int out_size)
{
    const float* F   = (const float*)d_in[0];
    const float* M   = (const float*)d_in[1];
    const float* Wm  = (const float*)d_in[2];
    const float* b   = (const float*)d_in[3];
    const float* lnw = (const float*)d_in[4];
    const float* lnb = (const float*)d_in[5];
    const float* rpb = (const float*)d_in[6];
    float* out = (float*)d_out;

    proj_kernel<<<dim3(NVOX/256, 2, 1), 256>>>(F, M, Wm, b, lnw, lnb);
    attn_kernel<<<dim3(1600, NHEADS, 1), 320>>>(rpb, out);
    if (out_size > NMOT) score_kernel<<<1, 256>>>(out);
}

// round 7
// speedup vs baseline: 2.0969x; 1.4577x over previous
#include <cuda_runtime.h>

// ---------------- problem constants ----------------
#define HWT    80
#define NVOX   (HWT*HWT*HWT)      // 512000
#define CIN    32
#define DIM    48
#define NHEADS 8
#define HD     6
#define NMOT   (NHEADS*3*NVOX)
#define LN_EPS 1e-5f

typedef unsigned long long ull;

// ---------------- packed fp32x2 helpers (sm_103a) ----------------
#define FMA_F32X2(d, a, b, c) \
    asm("fma.rn.f32x2 %0, %1, %2, %3;" : "=l"(d) : "l"(a), "l"(b), "l"(c))
#define PACK_F32X2(out, lo, hi) \
    asm("mov.b64 %0, {%1, %2};" : "=l"(out) : "f"(lo), "f"(hi))
#define UNPACK_F32X2(lo, hi, in) \
    asm("mov.b64 {%0, %1}, %2;" : "=f"(lo), "=f"(hi) : "l"(in))

// ---------------- scratch (static device globals) ----------------
// q/k pair-interleaved: [24 d-pairs][NVOX][2]
__device__ float g_q[(size_t)DIM*NVOX];
__device__ float g_k[(size_t)DIM*NVOX];
__device__ float g_partial[800*NHEADS];

// ============ kernel A: Linear(32->48)+LN, 4 vox x 12 d per thread ==========
__global__ __launch_bounds__(256, 3) void proj_kernel(
    const float* __restrict__ F, const float* __restrict__ M,
    const float* __restrict__ Wm, const float* __restrict__ bias,
    const float* __restrict__ lnw, const float* __restrict__ lnb)
{
    __shared__ float sWt[CIN*DIM];     // [c][d]
    __shared__ float sB[DIM], sLW[DIM], sLB[DIM];

    const int tid = threadIdx.x;
    for (int i = tid; i < DIM*CIN; i += 256) {
        const int d = i / CIN, c = i - d*CIN;
        sWt[c*DIM + d] = Wm[i];
    }
    if (tid < DIM) { sB[tid] = bias[tid]; sLW[tid] = lnw[tid]; sLB[tid] = lnb[tid]; }
    __syncthreads();

    const float* __restrict__ src = blockIdx.y ? M : F;
    float* __restrict__ dst = blockIdx.y ? g_k : g_q;
    const int v0 = blockIdx.x * 256;

    const int g = tid & 3;     // d-group: d in [12g, 12g+12)
    const int q = tid >> 2;    // voxel quad: v in [v0+4q, v0+4q+4)

    // direct coalesced x source: float4 per (c, quad)
    const float4* __restrict__ s4 = (const float4*)src + (v0 >> 2) + q;

    ull acc[24];               // [vox 4][d-pair 6]
#pragma unroll
    for (int j = 0; j < 6; j++) {
        ull b2;
        PACK_F32X2(b2, sB[12*g + 2*j], sB[12*g + 2*j + 1]);
        acc[j] = b2; acc[6+j] = b2; acc[12+j] = b2; acc[18+j] = b2;
    }

#pragma unroll 8
    for (int c = 0; c < CIN; c++) {
        const float4 xq = s4[(size_t)c*(NVOX/4)];
        ull xx0, xx1, xx2, xx3;
        PACK_F32X2(xx0, xq.x, xq.x);
        PACK_F32X2(xx1, xq.y, xq.y);
        PACK_F32X2(xx2, xq.z, xq.z);
        PACK_F32X2(xx3, xq.w, xq.w);
        const ulonglong2* __restrict__ wr = (const ulonglong2*)(sWt + c*DIM + 12*g);
#pragma unroll
        for (int j2 = 0; j2 < 3; j2++) {
            const ulonglong2 w2 = wr[j2];
            FMA_F32X2(acc[    2*j2  ], w2.x, xx0, acc[    2*j2  ]);
            FMA_F32X2(acc[    2*j2+1], w2.y, xx0, acc[    2*j2+1]);
            FMA_F32X2(acc[ 6 +2*j2  ], w2.x, xx1, acc[ 6 +2*j2  ]);
            FMA_F32X2(acc[ 6 +2*j2+1], w2.y, xx1, acc[ 6 +2*j2+1]);
            FMA_F32X2(acc[12 +2*j2  ], w2.x, xx2, acc[12 +2*j2  ]);
            FMA_F32X2(acc[12 +2*j2+1], w2.y, xx2, acc[12 +2*j2+1]);
            FMA_F32X2(acc[18 +2*j2  ], w2.x, xx3, acc[18 +2*j2  ]);
            FMA_F32X2(acc[18 +2*j2+1], w2.y, xx3, acc[18 +2*j2+1]);
        }
    }

    // LN stats: partial over 12 d, combine across the 4 d-group lanes via shfl
    float mu[4], rs[4];
#pragma unroll
    for (int i = 0; i < 4; i++) {
        float sum = 0.f, sq = 0.f;
#pragma unroll
        for (int j = 0; j < 6; j++) {
            float a, b;
            UNPACK_F32X2(a, b, acc[i*6 + j]);
            sum += a + b;
            sq = fmaf(a, a, sq);
            sq = fmaf(b, b, sq);
        }
        sum += __shfl_xor_sync(0xffffffffu, sum, 1);
        sq  += __shfl_xor_sync(0xffffffffu, sq, 1);
        sum += __shfl_xor_sync(0xffffffffu, sum, 2);
        sq  += __shfl_xor_sync(0xffffffffu, sq, 2);
        mu[i] = sum * (1.f/48.f);
        rs[i] = rsqrtf(sq * (1.f/48.f) - mu[i]*mu[i] + LN_EPS);
    }

    // pair-interleaved writeout
    const int vbase = v0 + 4*q;
#pragma unroll
    for (int j = 0; j < 6; j++) {
        const int d0 = 12*g + 2*j;
        const int p  = 6*g + j;
        const float w0l = sLW[d0], w1l = sLW[d0+1];
        const float b0l = sLB[d0], b1l = sLB[d0+1];
        float o[8];
#pragma unroll
        for (int i = 0; i < 4; i++) {
            float a, b;
            UNPACK_F32X2(a, b, acc[i*6 + j]);
            o[2*i  ] = (a - mu[i]) * rs[i] * w0l + b0l;
            o[2*i+1] = (b - mu[i]) * rs[i] * w1l + b1l;
        }
        float4* __restrict__ d4 = (float4*)(dst + ((size_t)p*NVOX + vbase)*2);
        d4[0] = make_float4(o[0], o[1], o[2], o[3]);
        d4[1] = make_float4(o[4], o[5], o[6], o[7]);
    }
}

// ======== kernel B: 27-neighbor attention, 2-t register blocking ============
#define LSTR   82            // float2 units per line (80 + 2 halo)
#define D2STRn (30*LSTR)     // 2460 float2 units per d-pair (30 lines)
#define SMEM_ATTN (3*D2STRn*8)   // 59040 B

__global__ __launch_bounds__(320, 3) void attn_kernel(
    const float* __restrict__ rpb, float* __restrict__ out)
{
    extern __shared__ float2 ks[];     // [3 d-pairs][30 lines][82 t]
    __shared__ float s_rpb[27];
    __shared__ float red[10];

    const int tid  = threadIdx.x;
    const int bx   = blockIdx.x;        // 0..799
    const int head = blockIdx.y;        // 0..7
    const int h    = bx / 10;
    const int w0   = (bx - h*10) * 8;   // 8-wide w strip
    const int pb   = head * 3;          // d-pair base

    if (tid < 27) s_rpb[tid] = rpb[head*27 + tid];

    // zero t-halo (t'=0, t'=81): 3*30*2 = 180 slots
    if (tid < 180) {
        const int d2 = tid / 60, r = tid - d2*60;
        const int line = r >> 1, e = r & 1;
        ks[d2*D2STRn + line*LSTR + (e ? 81 : 0)] = make_float2(0.f, 0.f);
    }

    // coalesced fill: 30 lines x 80 t, 3 d-pairs per index
    const float2* __restrict__ gk2 = (const float2*)g_k;
    for (int i = tid; i < 30*80; i += 320) {
        const int line = i / 80;
        const int tt   = i - line*80;
        const int l10  = line / 10;
        const int lh   = h + l10 - 1;
        const int lw   = w0 + (line - l10*10) - 1;
        const int sb   = line*LSTR + tt + 1;
        float2 k0 = make_float2(0.f,0.f), k1 = k0, k2 = k0;
        if (lh >= 0 && lh < HWT && lw >= 0 && lw < HWT) {
            const size_t gb = (size_t)pb*NVOX + (size_t)((lh*HWT + lw)*HWT + tt);
            k0 = gk2[gb];
            k1 = gk2[gb + NVOX];
            k2 = gk2[gb + 2*(size_t)NVOX];
        }
        ks[sb]            = k0;
        ks[D2STRn + sb]   = k1;
        ks[2*D2STRn + sb] = k2;
    }

    // q for this thread's two voxels (t, t+1): three LDG.128
    const int u  = tid % 40;
    const int wl = tid / 40;            // 0..7
    const int t  = 2*u;
    const int v  = (h*HWT + (w0 + wl))*HWT + t;
    const ull* __restrict__ gq = (const ull*)g_q;
    const ulonglong2 Q0 = *(const ulonglong2*)(gq + (size_t)(pb + 0)*NVOX + v);
    const ulonglong2 Q1 = *(const ulonglong2*)(gq + (size_t)(pb + 1)*NVOX + v);
    const ulonglong2 Q2 = *(const ulonglong2*)(gq + (size_t)(pb + 2)*NVOX + v);
    __syncthreads();

    const ull* __restrict__ kb = (const ull*)ks;
    float sa = 0.f, mxa = 0.f, mya = 0.f, mza = 0.f, sca = 0.f;
    float sb_ = 0.f, mxb = 0.f, myb = 0.f, mzb = 0.f, scb = 0.f;

#pragma unroll
    for (int o9 = 0; o9 < 9; o9++) {
        const int oi = o9 / 3, oj = o9 % 3;
        const int base = (oi*10 + wl + oj)*LSTR + t;
        ull la0 = 0ull, la1 = 0ull, la2 = 0ull;
        ull lb0 = 0ull, lb1 = 0ull, lb2 = 0ull;
#pragma unroll
        for (int d2 = 0; d2 < 3; d2++) {
            const ulonglong2 A = *(const ulonglong2*)(kb + d2*D2STRn + base);
            const ulonglong2 B = *(const ulonglong2*)(kb + d2*D2STRn + base + 2);
            const ull qa = (d2 == 0) ? Q0.x : ((d2 == 1) ? Q1.x : Q2.x);
            const ull qb = (d2 == 0) ? Q0.y : ((d2 == 1) ? Q1.y : Q2.y);
            FMA_F32X2(la0, qa, A.x, la0);
            FMA_F32X2(la1, qa, A.y, la1);
            FMA_F32X2(la2, qa, B.x, la2);
            FMA_F32X2(lb0, qb, A.y, lb0);
            FMA_F32X2(lb1, qb, B.x, lb1);
            FMA_F32X2(lb2, qb, B.y, lb2);
        }
#pragma unroll
        for (int ol = 0; ol < 3; ol++) {
            const ull lva = (ol == 0) ? la0 : ((ol == 1) ? la1 : la2);
            const ull lvb = (ol == 0) ? lb0 : ((ol == 1) ? lb1 : lb2);
            float x1, x2, y1, y2;
            UNPACK_F32X2(x1, x2, lva);
            UNPACK_F32X2(y1, y2, lvb);
            const float r  = s_rpb[o9*3 + ol];
            const float aa = x1 + x2 + r;
            const float ab = y1 + y2 + r;
            if (o9 == 4 && ol == 2) { sca = aa; scb = ab; }   // score channel o=14
            const float ea = __expf(aa);   // max-free softmax: |a| is O(10)
            const float eb = __expf(ab);
            sa += ea;  sb_ += eb;
            if (oi == 0)      { mxa -= ea; mxb -= eb; }
            else if (oi == 2) { mxa += ea; mxb += eb; }
            if (oj == 0)      { mya -= ea; myb -= eb; }
            else if (oj == 2) { mya += ea; myb += eb; }
            if (ol == 0)      { mza -= ea; mzb -= eb; }
            else if (ol == 2) { mza += ea; mzb += eb; }
        }
    }

    const float ia = __fdividef(1.f, sa);
    const float ib = __fdividef(1.f, sb_);
    *(float2*)&out[(size_t)(head*3 + 0)*NVOX + v] = make_float2(mxa*ia, mxb*ib);
    *(float2*)&out[(size_t)(head*3 + 1)*NVOX + v] = make_float2(mya*ia, myb*ib);
    *(float2*)&out[(size_t)(head*3 + 2)*NVOX + v] = make_float2(mza*ia, mzb*ib);

    // deterministic block reduction of score channel
    float sc = sca + scb;
#pragma unroll
    for (int off = 16; off; off >>= 1) sc += __shfl_down_sync(0xffffffffu, sc, off);
    if ((tid & 31) == 0) red[tid >> 5] = sc;
    __syncthreads();
    if (tid < 32) {
        float v2 = (tid < 10) ? red[tid] : 0.f;
#pragma unroll
        for (int off = 16; off; off >>= 1) v2 += __shfl_down_sync(0xffffffffu, v2, off);
        if (tid == 0) g_partial[head*800 + bx] = v2;
    }
}

// ---------------- kernel C: deterministic final score reduction -------------
__global__ __launch_bounds__(256) void score_kernel(float* __restrict__ out)
{
    __shared__ double sd[256];
    const int tid = threadIdx.x;
    double a = 0.0;
    for (int i = tid; i < 800*NHEADS; i += 256) a += (double)g_partial[i];
    sd[tid] = a;
    __syncthreads();
    for (int s = 128; s > 0; s >>= 1) {
        if (tid < s) sd[tid] += sd[tid + s];
        __syncthreads();
    }
    if (tid == 0) out[NMOT] = (float)(sd[0] * (1.0 / 4096000.0));
}

// ---------------- launch -----------------------------------------------------
extern "C" void kernel_launch(void* const* d_in, const int* in_sizes, int n_in,
                              void* d_out, int out_size)
{
    const float* F   = (const float*)d_in[0];
    const float* M   = (const float*)d_in[1];
    const float* Wm  = (const float*)d_in[2];
    const float* b   = (const float*)d_in[3];
    const float* lnw = (const float*)d_in[4];
    const float* lnb = (const float*)d_in[5];
    const float* rpb = (const float*)d_in[6];
    float* out = (float*)d_out;

    cudaFuncSetAttribute(attn_kernel, cudaFuncAttributeMaxDynamicSharedMemorySize, SMEM_ATTN);

    proj_kernel<<<dim3(NVOX/256, 2, 1), 256>>>(F, M, Wm, b, lnw, lnb);
    attn_kernel<<<dim3(800, NHEADS, 1), 320, SMEM_ATTN>>>(rpb, out);
    if (out_size > NMOT) score_kernel<<<1, 256>>>(out);
}

// round 8
// speedup vs baseline: 2.1993x; 1.0489x over previous
#include <cuda_runtime.h>

// ---------------- problem constants ----------------
#define HWT    80
#define NVOX   (HWT*HWT*HWT)      // 512000
#define CIN    32
#define DIM    48
#define NHEADS 8
#define HD     6
#define NMOT   (NHEADS*3*NVOX)
#define LN_EPS 1e-5f

typedef unsigned long long ull;

// ---------------- packed fp32x2 helpers (sm_103a) ----------------
#define FMA_F32X2(d, a, b, c) \
    asm("fma.rn.f32x2 %0, %1, %2, %3;" : "=l"(d) : "l"(a), "l"(b), "l"(c))
#define PACK_F32X2(out, lo, hi) \
    asm("mov.b64 %0, {%1, %2};" : "=l"(out) : "f"(lo), "f"(hi))
#define UNPACK_F32X2(lo, hi, in) \
    asm("mov.b64 {%0, %1}, %2;" : "=f"(lo), "=f"(hi) : "l"(in))

// ---------------- cp.async helpers ----------------
__device__ __forceinline__ void cp_async16(void* s, const void* g) {
    unsigned saddr = (unsigned)__cvta_generic_to_shared(s);
    asm volatile("cp.async.cg.shared.global [%0], [%1], 16;\n" :: "r"(saddr), "l"(g));
}
#define CP_COMMIT()  asm volatile("cp.async.commit_group;\n" ::: "memory")
#define CP_WAIT(n)   asm volatile("cp.async.wait_group %0;\n" :: "n"(n) : "memory")

// ---------------- scratch (static device globals) ----------------
// q/k pair-interleaved: [24 d-pairs][NVOX][2]
__device__ float g_q[(size_t)DIM*NVOX];
__device__ float g_k[(size_t)DIM*NVOX];
__device__ float g_partial[800*NHEADS];

// ============ kernel A: Linear(32->48)+LN, cp.async x pipeline ==============
#define CSTAGE 4      // c per stage
#define NST    4      // ring depth
#define NSLICE (CIN/CSTAGE)   // 8

__global__ __launch_bounds__(256, 3) void proj_kernel(
    const float* __restrict__ F, const float* __restrict__ M,
    const float* __restrict__ Wm, const float* __restrict__ bias,
    const float* __restrict__ lnw, const float* __restrict__ lnb)
{
    __shared__ float sWt[CIN*DIM];            // [c][d]
    __shared__ float sX[NST][CSTAGE*256];     // x ring: [stage][4 c][256 vox]
    __shared__ float sB[DIM], sLW[DIM], sLB[DIM];

    const int tid = threadIdx.x;
    const float* __restrict__ src = blockIdx.y ? M : F;
    float* __restrict__ dst = blockIdx.y ? g_k : g_q;
    const int v0 = blockIdx.x * 256;

    // prefetch address for this thread: c-row = tid>>6 (4 rows), quad = tid&63
    const int pf_c = tid >> 6;
    const int pf_v = (tid & 63) * 4;
    const float* __restrict__ pf_src = src + (size_t)pf_c * NVOX + v0 + pf_v;
    float* const pf_dst_row = &sX[0][pf_c * 256 + pf_v];

    // kick off 3 stages immediately (slices 0,1,2)
    cp_async16(&sX[0][pf_c*256 + pf_v], pf_src);                      CP_COMMIT();
    cp_async16(&sX[1][pf_c*256 + pf_v], pf_src + (size_t)CSTAGE*NVOX); CP_COMMIT();
    cp_async16(&sX[2][pf_c*256 + pf_v], pf_src + (size_t)2*CSTAGE*NVOX); CP_COMMIT();

    // weights / LN params while loads fly
    for (int i = tid; i < DIM*CIN; i += 256) {
        const int d = i / CIN, c = i - d*CIN;
        sWt[c*DIM + d] = Wm[i];
    }
    if (tid < DIM) { sB[tid] = bias[tid]; sLW[tid] = lnw[tid]; sLB[tid] = lnb[tid]; }

    const int g = tid & 3;     // d-group: d in [12g, 12g+12)
    const int q = tid >> 2;    // voxel quad

    ull acc[24];               // [vox 4][d-pair 6]
#pragma unroll
    for (int j = 0; j < 6; j++) {
        ull b2;
        PACK_F32X2(b2, Wm == 0 ? 0.f : 0.f, 0.f);   // placeholder overwritten below
        (void)b2;
    }
    // (init accs after first sync so sB is visible)

#pragma unroll
    for (int cs = 0; cs < NSLICE; cs++) {
        if (cs <= NSLICE-3) { CP_WAIT(2); }
        else if (cs == NSLICE-2) { CP_WAIT(1); }
        else { CP_WAIT(0); }
        __syncthreads();

        if (cs == 0) {
            // accumulator init (sB now visible)
#pragma unroll
            for (int j = 0; j < 6; j++) {
                ull b2;
                PACK_F32X2(b2, sB[12*g + 2*j], sB[12*g + 2*j + 1]);
                acc[j] = b2; acc[6+j] = b2; acc[12+j] = b2; acc[18+j] = b2;
            }
        }

        // refill the buffer freed by slice cs-1 with slice cs+3
        if (cs + 3 < NSLICE) {
            cp_async16(pf_dst_row + ((cs+3) & (NST-1)) * (CSTAGE*256),
                       pf_src + (size_t)(cs+3)*CSTAGE*NVOX);
            CP_COMMIT();
        }

        const float* __restrict__ xb = sX[cs & (NST-1)];
#pragma unroll
        for (int cl = 0; cl < CSTAGE; cl++) {
            const int c = cs*CSTAGE + cl;
            const float4 xq = *(const float4*)(xb + cl*256 + 4*q);
            ull xx0, xx1, xx2, xx3;
            PACK_F32X2(xx0, xq.x, xq.x);
            PACK_F32X2(xx1, xq.y, xq.y);
            PACK_F32X2(xx2, xq.z, xq.z);
            PACK_F32X2(xx3, xq.w, xq.w);
            const ulonglong2* __restrict__ wr = (const ulonglong2*)(sWt + c*DIM + 12*g);
#pragma unroll
            for (int j2 = 0; j2 < 3; j2++) {
                const ulonglong2 w2 = wr[j2];
                FMA_F32X2(acc[    2*j2  ], w2.x, xx0, acc[    2*j2  ]);
                FMA_F32X2(acc[    2*j2+1], w2.y, xx0, acc[    2*j2+1]);
                FMA_F32X2(acc[ 6 +2*j2  ], w2.x, xx1, acc[ 6 +2*j2  ]);
                FMA_F32X2(acc[ 6 +2*j2+1], w2.y, xx1, acc[ 6 +2*j2+1]);
                FMA_F32X2(acc[12 +2*j2  ], w2.x, xx2, acc[12 +2*j2  ]);
                FMA_F32X2(acc[12 +2*j2+1], w2.y, xx2, acc[12 +2*j2+1]);
                FMA_F32X2(acc[18 +2*j2  ], w2.x, xx3, acc[18 +2*j2  ]);
                FMA_F32X2(acc[18 +2*j2+1], w2.y, xx3, acc[18 +2*j2+1]);
            }
        }
    }

    // LN stats: partial over 12 d, combine across 4 d-group lanes via shfl
    float mu[4], rs[4];
#pragma unroll
    for (int i = 0; i < 4; i++) {
        float sum = 0.f, sq = 0.f;
#pragma unroll
        for (int j = 0; j < 6; j++) {
            float a, b;
            UNPACK_F32X2(a, b, acc[i*6 + j]);
            sum += a + b;
            sq = fmaf(a, a, sq);
            sq = fmaf(b, b, sq);
        }
        sum += __shfl_xor_sync(0xffffffffu, sum, 1);
        sq  += __shfl_xor_sync(0xffffffffu, sq, 1);
        sum += __shfl_xor_sync(0xffffffffu, sum, 2);
        sq  += __shfl_xor_sync(0xffffffffu, sq, 2);
        mu[i] = sum * (1.f/48.f);
        rs[i] = rsqrtf(sq * (1.f/48.f) - mu[i]*mu[i] + LN_EPS);
    }

    // pair-interleaved writeout, streaming stores
    const int vbase = v0 + 4*q;
#pragma unroll
    for (int j = 0; j < 6; j++) {
        const int d0 = 12*g + 2*j;
        const int p  = 6*g + j;
        const float w0l = sLW[d0], w1l = sLW[d0+1];
        const float b0l = sLB[d0], b1l = sLB[d0+1];
        float o[8];
#pragma unroll
        for (int i = 0; i < 4; i++) {
            float a, b;
            UNPACK_F32X2(a, b, acc[i*6 + j]);
            o[2*i  ] = (a - mu[i]) * rs[i] * w0l + b0l;
            o[2*i+1] = (b - mu[i]) * rs[i] * w1l + b1l;
        }
        float4* __restrict__ d4 = (float4*)(dst + ((size_t)p*NVOX + vbase)*2);
        __stcs(d4,     make_float4(o[0], o[1], o[2], o[3]));
        __stcs(d4 + 1, make_float4(o[4], o[5], o[6], o[7]));
    }
}

// ======== kernel B: 27-neighbor attention, 2-t register blocking ============
#define LSTR   82            // float2 units per line (80 + 2 halo)
#define D2STRn (30*LSTR)     // 2460 float2 units per d-pair (30 lines)
#define SMEM_ATTN (3*D2STRn*8)   // 59040 B

__global__ __launch_bounds__(320, 3) void attn_kernel(
    const float* __restrict__ rpb, float* __restrict__ out)
{
    extern __shared__ float2 ks[];     // [3 d-pairs][30 lines][82 t]
    __shared__ float s_rpb[27];
    __shared__ float red[10];

    const int tid  = threadIdx.x;
    const int bx   = blockIdx.x;        // 0..799
    const int head = blockIdx.y;        // 0..7
    const int h    = bx / 10;
    const int w0   = (bx - h*10) * 8;   // 8-wide w strip
    const int pb   = head * 3;          // d-pair base

    if (tid < 27) s_rpb[tid] = rpb[head*27 + tid];

    // zero t-halo (t'=0, t'=81): 3*30*2 = 180 slots
    if (tid < 180) {
        const int d2 = tid / 60, r = tid - d2*60;
        const int line = r >> 1, e = r & 1;
        ks[d2*D2STRn + line*LSTR + (e ? 81 : 0)] = make_float2(0.f, 0.f);
    }

    // coalesced fill: 30 lines x 80 t, 3 d-pairs per index
    const float2* __restrict__ gk2 = (const float2*)g_k;
    for (int i = tid; i < 30*80; i += 320) {
        const int line = i / 80;
        const int tt   = i - line*80;
        const int l10  = line / 10;
        const int lh   = h + l10 - 1;
        const int lw   = w0 + (line - l10*10) - 1;
        const int sb   = line*LSTR + tt + 1;
        float2 k0 = make_float2(0.f,0.f), k1 = k0, k2 = k0;
        if (lh >= 0 && lh < HWT && lw >= 0 && lw < HWT) {
            const size_t gb = (size_t)pb*NVOX + (size_t)((lh*HWT + lw)*HWT + tt);
            k0 = gk2[gb];
            k1 = gk2[gb + NVOX];
            k2 = gk2[gb + 2*(size_t)NVOX];
        }
        ks[sb]            = k0;
        ks[D2STRn + sb]   = k1;
        ks[2*D2STRn + sb] = k2;
    }

    // q for this thread's two voxels (t, t+1): three LDG.128
    const int u  = tid % 40;
    const int wl = tid / 40;            // 0..7
    const int t  = 2*u;
    const int v  = (h*HWT + (w0 + wl))*HWT + t;
    const ull* __restrict__ gq = (const ull*)g_q;
    const ulonglong2 Q0 = *(const ulonglong2*)(gq + (size_t)(pb + 0)*NVOX + v);
    const ulonglong2 Q1 = *(const ulonglong2*)(gq + (size_t)(pb + 1)*NVOX + v);
    const ulonglong2 Q2 = *(const ulonglong2*)(gq + (size_t)(pb + 2)*NVOX + v);
    __syncthreads();

    const ull* __restrict__ kb = (const ull*)ks;
    float sa = 0.f, mxa = 0.f, mya = 0.f, mza = 0.f, sca = 0.f;
    float sb_ = 0.f, mxb = 0.f, myb = 0.f, mzb = 0.f, scb = 0.f;

#pragma unroll
    for (int o9 = 0; o9 < 9; o9++) {
        const int oi = o9 / 3, oj = o9 % 3;
        const int base = (oi*10 + wl + oj)*LSTR + t;
        ull la0 = 0ull, la1 = 0ull, la2 = 0ull;
        ull lb0 = 0ull, lb1 = 0ull, lb2 = 0ull;
#pragma unroll
        for (int d2 = 0; d2 < 3; d2++) {
            const ulonglong2 A = *(const ulonglong2*)(kb + d2*D2STRn + base);
            const ulonglong2 B = *(const ulonglong2*)(kb + d2*D2STRn + base + 2);
            const ull qa = (d2 == 0) ? Q0.x : ((d2 == 1) ? Q1.x : Q2.x);
            const ull qb = (d2 == 0) ? Q0.y : ((d2 == 1) ? Q1.y : Q2.y);
            FMA_F32X2(la0, qa, A.x, la0);
            FMA_F32X2(la1, qa, A.y, la1);
            FMA_F32X2(la2, qa, B.x, la2);
            FMA_F32X2(lb0, qb, A.y, lb0);
            FMA_F32X2(lb1, qb, B.x, lb1);
            FMA_F32X2(lb2, qb, B.y, lb2);
        }
#pragma unroll
        for (int ol = 0; ol < 3; ol++) {
            const ull lva = (ol == 0) ? la0 : ((ol == 1) ? la1 : la2);
            const ull lvb = (ol == 0) ? lb0 : ((ol == 1) ? lb1 : lb2);
            float x1, x2, y1, y2;
            UNPACK_F32X2(x1, x2, lva);
            UNPACK_F32X2(y1, y2, lvb);
            const float r  = s_rpb[o9*3 + ol];
            const float aa = x1 + x2 + r;
            const float ab = y1 + y2 + r;
            if (o9 == 4 && ol == 2) { sca = aa; scb = ab; }   // score channel o=14
            const float ea = __expf(aa);   // max-free softmax: |a| is O(10)
            const float eb = __expf(ab);
            sa += ea;  sb_ += eb;
            if (oi == 0)      { mxa -= ea; mxb -= eb; }
            else if (oi == 2) { mxa += ea; mxb += eb; }
            if (oj == 0)      { mya -= ea; myb -= eb; }
            else if (oj == 2) { mya += ea; myb += eb; }
            if (ol == 0)      { mza -= ea; mzb -= eb; }
            else if (ol == 2) { mza += ea; mzb += eb; }
        }
    }

    const float ia = __fdividef(1.f, sa);
    const float ib = __fdividef(1.f, sb_);
    *(float2*)&out[(size_t)(head*3 + 0)*NVOX + v] = make_float2(mxa*ia, mxb*ib);
    *(float2*)&out[(size_t)(head*3 + 1)*NVOX + v] = make_float2(mya*ia, myb*ib);
    *(float2*)&out[(size_t)(head*3 + 2)*NVOX + v] = make_float2(mza*ia, mzb*ib);

    // deterministic block reduction of score channel
    float sc = sca + scb;
#pragma unroll
    for (int off = 16; off; off >>= 1) sc += __shfl_down_sync(0xffffffffu, sc, off);
    if ((tid & 31) == 0) red[tid >> 5] = sc;
    __syncthreads();
    if (tid < 32) {
        float v2 = (tid < 10) ? red[tid] : 0.f;
#pragma unroll
        for (int off = 16; off; off >>= 1) v2 += __shfl_down_sync(0xffffffffu, v2, off);
        if (tid == 0) g_partial[head*800 + bx] = v2;
    }
}

// ---------------- kernel C: deterministic final score reduction -------------
__global__ __launch_bounds__(256) void score_kernel(float* __restrict__ out)
{
    __shared__ double sd[256];
    const int tid = threadIdx.x;
    double a = 0.0;
    for (int i = tid; i < 800*NHEADS; i += 256) a += (double)g_partial[i];
    sd[tid] = a;
    __syncthreads();
    for (int s = 128; s > 0; s >>= 1) {
        if (tid < s) sd[tid] += sd[tid + s];
        __syncthreads();
    }
    if (tid == 0) out[NMOT] = (float)(sd[0] * (1.0 / 4096000.0));
}

// ---------------- launch -----------------------------------------------------
extern "C" void kernel_launch(void* const* d_in, const int* in_sizes, int n_in,
                              void* d_out, int out_size)
{
    const float* F   = (const float*)d_in[0];
    const float* M   = (const float*)d_in[1];
    const float* Wm  = (const float*)d_in[2];
    const float* b   = (const float*)d_in[3];
    const float* lnw = (const float*)d_in[4];
    const float* lnb = (const float*)d_in[5];
    const float* rpb = (const float*)d_in[6];
    float* out = (float*)d_out;

    cudaFuncSetAttribute(attn_kernel, cudaFuncAttributeMaxDynamicSharedMemorySize, SMEM_ATTN);

    proj_kernel<<<dim3(NVOX/256, 2, 1), 256>>>(F, M, Wm, b, lnw, lnb);
    attn_kernel<<<dim3(800, NHEADS, 1), 320, SMEM_ATTN>>>(rpb, out);
    if (out_size > NMOT) score_kernel<<<1, 256>>>(out);
}